// round 11
// baseline (speedup 1.0000x reference)
#include <cuda_runtime.h>
#include <cuda_bf16.h>

// T=50, H=W=8, NH=16, B=8, TP=TF=8, HIDDEN=512, RPE_COEF=16
#define NROW    22275         // 99*15*15
#define NROWP   22400         // 175 MLP blocks * 128 rows
#define NHEAD   16
#define HIDDEN  512
#define W2TS    520           // bf16 row stride for transposed W2 (conflict-free)
#define NMLPB   175
#define NGATB   8192

// Scratch: g_rpt[nh][row] = 16*sigmoid( (relu(rct@W1+b1)@W2)[row][nh] )
__device__ float g_rpt[NHEAD * NROWP];
// Producer->consumer flags (one per 128-row chunk) + self-reset counter.
__device__ int g_flag[NMLPB];
__device__ int g_done;

// pack two fp32 -> bf16x2 (lo = first arg)
__device__ __forceinline__ unsigned bfpack(float lo, float hi) {
    unsigned r;
    asm("cvt.rn.bf16x2.f32 %0, %1, %2;" : "=r"(r) : "f"(hi), "f"(lo));
    return r;
}

// ---------------------------------------------------------------------------
// ONE fused kernel. Blocks 0..174: MLP producer (128 rows each, HMMA layer 2).
// Blocks 175..: gather consumers; each waits only on the <=3 row-chunk flags
// covering its 225-float table slice, then streams its 64x64 output tile.
// ---------------------------------------------------------------------------
__global__ void __launch_bounds__(256) fused_kernel(
    const int*   __restrict__ ptc,   // [B, 8] (non-positive; time = -ptc)
    const int*   __restrict__ ftc,   // [B, 8]
    const float* __restrict__ rct,   // [NROW, 3]
    const float* __restrict__ W1,    // [3, 512]
    const float* __restrict__ b1,    // [512]
    const float* __restrict__ W2,    // [512, 16]
    float4*      __restrict__ out)   // [B, 16, 512, 512] / 4
{
    __shared__ __align__(16) char smem_raw[8192 + NHEAD * W2TS * 2];  // 24.4 KB
    const int tid = threadIdx.x;

    if (blockIdx.x < NMLPB) {
        // ================= MLP producer =================
        float4*        sW14 = reinterpret_cast<float4*>(smem_raw);
        __nv_bfloat16* sW2T = reinterpret_cast<__nv_bfloat16*>(smem_raw + 8192);

        const int wid  = tid >> 5;           // 0..7, warp -> 16 rows
        const int lane = tid & 31;
        const int g    = lane >> 2;          // 0..7
        const int t    = lane & 3;           // 0..3
        const int row0 = blockIdx.x * 128;

        // Stage W1|b1 (512 float4) and W2 transposed bf16 [n][k]
        #pragma unroll
        for (int i = tid; i < HIDDEN; i += 256)
            sW14[i] = make_float4(__ldg(W1 + i), __ldg(W1 + HIDDEN + i),
                                  __ldg(W1 + 2 * HIDDEN + i), __ldg(b1 + i));
        #pragma unroll
        for (int i = tid; i < HIDDEN * NHEAD; i += 256) {
            const int k = i >> 4, n = i & 15;
            sW2T[n * W2TS + k] = __float2bfloat16(__ldg(W2 + k * NHEAD + n));
        }

        const int rw = row0 + wid * 16;
        const int r0 = rw + g, r1 = r0 + 8;
        float cA0 = 0.f, cA1 = 0.f, cA2 = 0.f, cB0 = 0.f, cB1 = 0.f, cB2 = 0.f;
        if (r0 < NROW) { cA0 = __ldg(rct + r0 * 3 + 0);
                         cA1 = __ldg(rct + r0 * 3 + 1);
                         cA2 = __ldg(rct + r0 * 3 + 2); }
        if (r1 < NROW) { cB0 = __ldg(rct + r1 * 3 + 0);
                         cB1 = __ldg(rct + r1 * 3 + 1);
                         cB2 = __ldg(rct + r1 * 3 + 2); }
        __syncthreads();

        float d0[4] = {0.f, 0.f, 0.f, 0.f};   // nh 0-7 tile
        float d1[4] = {0.f, 0.f, 0.f, 0.f};   // nh 8-15 tile

        #pragma unroll 4
        for (int ch = 0; ch < 32; ch++) {
            const int h0 = ch * 16 + 2 * t;   // k: h0, h0+1, h0+8, h0+9
            float hA[4], hB[4];
            #pragma unroll
            for (int q = 0; q < 4; q++) {
                const int h = h0 + (q & 1) + (q >> 1) * 8;
                const float4 wc = sW14[h];
                hA[q] = fmaxf(fmaf(cA2, wc.z, fmaf(cA1, wc.y, fmaf(cA0, wc.x, wc.w))), 0.f);
                hB[q] = fmaxf(fmaf(cB2, wc.z, fmaf(cB1, wc.y, fmaf(cB0, wc.x, wc.w))), 0.f);
            }
            const unsigned a0 = bfpack(hA[0], hA[1]);
            const unsigned a1 = bfpack(hB[0], hB[1]);
            const unsigned a2 = bfpack(hA[2], hA[3]);
            const unsigned a3 = bfpack(hB[2], hB[3]);
            const unsigned bA0 = *reinterpret_cast<const unsigned*>(&sW2T[g * W2TS + h0]);
            const unsigned bA1 = *reinterpret_cast<const unsigned*>(&sW2T[g * W2TS + h0 + 8]);
            const unsigned bB0 = *reinterpret_cast<const unsigned*>(&sW2T[(g + 8) * W2TS + h0]);
            const unsigned bB1 = *reinterpret_cast<const unsigned*>(&sW2T[(g + 8) * W2TS + h0 + 8]);
            asm volatile(
                "mma.sync.aligned.m16n8k16.row.col.f32.bf16.bf16.f32 "
                "{%0,%1,%2,%3}, {%4,%5,%6,%7}, {%8,%9}, {%0,%1,%2,%3};"
                : "+f"(d0[0]), "+f"(d0[1]), "+f"(d0[2]), "+f"(d0[3])
                : "r"(a0), "r"(a1), "r"(a2), "r"(a3), "r"(bA0), "r"(bA1));
            asm volatile(
                "mma.sync.aligned.m16n8k16.row.col.f32.bf16.bf16.f32 "
                "{%0,%1,%2,%3}, {%4,%5,%6,%7}, {%8,%9}, {%0,%1,%2,%3};"
                : "+f"(d1[0]), "+f"(d1[1]), "+f"(d1[2]), "+f"(d1[3])
                : "r"(a0), "r"(a1), "r"(a2), "r"(a3), "r"(bB0), "r"(bB1));
        }

        #pragma unroll
        for (int j = 0; j < 4; j++) {
            d0[j] = 16.f / (1.f + __expf(-d0[j]));
            d1[j] = 16.f / (1.f + __expf(-d1[j]));
        }
        const int nh0 = 2 * t;
        g_rpt[(nh0    ) * NROWP + r0] = d0[0];
        g_rpt[(nh0 + 1) * NROWP + r0] = d0[1];
        g_rpt[(nh0    ) * NROWP + r1] = d0[2];
        g_rpt[(nh0 + 1) * NROWP + r1] = d0[3];
        g_rpt[(nh0 + 8) * NROWP + r0] = d1[0];
        g_rpt[(nh0 + 9) * NROWP + r0] = d1[1];
        g_rpt[(nh0 + 8) * NROWP + r1] = d1[2];
        g_rpt[(nh0 + 9) * NROWP + r1] = d1[3];

        // Publish this 128-row chunk.
        __syncthreads();
        if (tid == 0) {
            __threadfence();
            atomicExch(&g_flag[blockIdx.x], 1);
        }
    } else {
        // ================= gather consumer =================
        float4* vtab = reinterpret_cast<float4*>(smem_raw);   // 240 entries

        const int blk = blockIdx.x - NMLPB;
        const int tp = blk & 7;
        const int tf = (blk >> 3) & 7;
        const int nh = (blk >> 6) & 15;
        const int b  = blk >> 10;

        const int t_f =  __ldg(ftc + b * 8 + tf);
        const int t_p = -__ldg(ptc + b * 8 + tp);
        const int rbase = (t_f + t_p) * 225;

        // Wait for the <=3 producer chunks covering rows [rbase, rbase+224].
        if (tid == 0) {
            const int first = rbase >> 7;
            const int last  = (rbase + 224) >> 7;
            for (int f = first; f <= last; f++)
                while (((volatile int*)g_flag)[f] == 0) __nanosleep(64);
            __threadfence();
        }
        __syncthreads();

        const float* __restrict__ src = g_rpt + nh * NROWP + rbase;
        if (tid < 240) {
            const int wf  = tid / 30;
            const int rem = tid - wf * 30;
            const int dh7 = rem >> 1;
            const int par = rem & 1;                       // wp0 = par*4
            const int si  = dh7 * 15 + wf - par * 4 + 7;   // in [3, 224]
            vtab[tid] = make_float4(__ldg(src + si),     __ldg(src + si - 1),
                                    __ldg(src + si - 2), __ldg(src + si - 3));
        }
        __syncthreads();

        const int c4    = tid & 15;
        const int fhw0  = tid >> 4;            // 0..15
        const int wf    = fhw0 & 7;
        const int b0    = fhw0 >> 3;           // 0 or 1
        const int hp    = c4 >> 1;
        const int par   = c4 & 1;
        const int base0 = wf * 30 + (b0 - hp + 7) * 2 + par;

        float4* __restrict__ p =
            out + ((((b * NHEAD + nh) * 512 + tf * 64) * 512 + tp * 64) >> 2)
                + fhw0 * 128 + c4;

        #pragma unroll
        for (int k = 0; k < 4; k++) {
            __stcs(p, vtab[base0 + 4 * k]);    // hf = b0 + 2k, always <= 7
            p += 2048;                          // fhw += 16
        }

        // Self-reset for the next graph replay: the LAST gather block zeroes
        // all flags and the counter (deterministic across calls).
        __syncthreads();
        if (tid == 0) {
            if (atomicAdd(&g_done, 1) == NGATB - 1) {
                #pragma unroll 5
                for (int f = 0; f < NMLPB; f++) g_flag[f] = 0;
                __threadfence();
                g_done = 0;
            }
        }
    }
}

// ---------------------------------------------------------------------------
// Launch. Input order: ptc, ftc, W1, b1, W2, rct, rpi_table (unused).
// ---------------------------------------------------------------------------
extern "C" void kernel_launch(void* const* d_in, const int* in_sizes, int n_in,
                              void* d_out, int out_size)
{
    const int*   ptc = (const int*)  d_in[0];
    const int*   ftc = (const int*)  d_in[1];
    const float* W1  = (const float*)d_in[2];
    const float* b1  = (const float*)d_in[3];
    const float* W2  = (const float*)d_in[4];
    const float* rct = (const float*)d_in[5];

    // Blocks 0..174: MLP producers (dispatched first -> no consumer deadlock).
    // Blocks 175..8366: gather consumers.
    fused_kernel<<<NMLPB + NGATB, 256>>>(ptc, ftc, rct, W1, b1, W2,
                                         (float4*)d_out);
}

// round 13
// speedup vs baseline: 1.2413x; 1.2413x over previous
#include <cuda_runtime.h>
#include <cuda_bf16.h>

// T=50, H=W=8, NH=16, B=8, TP=TF=8, HIDDEN=512, RPE_COEF=16
#define NROW   22275          // 99*15*15
#define NROWP  22400          // 350 blocks * 64 rows
#define NHEAD  16
#define HIDDEN 512
#define W2TS   520            // bf16 row stride for transposed W2 (conflict-free)

// Scratch: g_rpt[nh][row] = 16*sigmoid( (relu(rct@W1+b1)@W2)[row][nh] )
__device__ float g_rpt[NHEAD * NROWP];

// pack two fp32 -> bf16x2 (lo = first arg)
__device__ __forceinline__ unsigned bfpack(float lo, float hi) {
    unsigned r;
    asm("cvt.rn.bf16x2.f32 %0, %1, %2;" : "=r"(r) : "f"(hi), "f"(lo));
    return r;
}

// ---------------------------------------------------------------------------
// Kernel 1: FUSED cpb MLP with tensor-core layer 2 (identical to R10 winner),
// plus an early PDL trigger so the gather grid is scheduled underneath us.
// ---------------------------------------------------------------------------
__global__ void __launch_bounds__(128) mlp_kernel(
    const float* __restrict__ rct,   // [NROW, 3]
    const float* __restrict__ W1,    // [3, 512]
    const float* __restrict__ b1,    // [512]
    const float* __restrict__ W2)    // [512, 16]
{
#if __CUDA_ARCH__ >= 900
    cudaTriggerProgrammaticLaunchCompletion();   // let gather's prologue overlap
#endif
    __shared__ float4 sW14[HIDDEN];                       // 8 KB  {W1_0,W1_1,W1_2,b1}[h]
    __shared__ __align__(16) __nv_bfloat16 sW2T[NHEAD * W2TS];  // 16.25 KB  [n][k]

    const int tid  = threadIdx.x;
    const int wid  = tid >> 5;
    const int lane = tid & 31;
    const int g    = lane >> 2;          // 0..7
    const int t    = lane & 3;           // 0..3
    const int row0 = blockIdx.x * 64;

    #pragma unroll
    for (int i = tid; i < HIDDEN; i += 128)
        sW14[i] = make_float4(__ldg(W1 + i), __ldg(W1 + HIDDEN + i),
                              __ldg(W1 + 2 * HIDDEN + i), __ldg(b1 + i));
    #pragma unroll
    for (int i = tid; i < HIDDEN * NHEAD; i += 128) {
        const int k = i >> 4, n = i & 15;
        sW2T[n * W2TS + k] = __float2bfloat16(__ldg(W2 + k * NHEAD + n));
    }

    const int rw = row0 + wid * 16;
    const int r0 = rw + g, r1 = r0 + 8;
    float cA0 = 0.f, cA1 = 0.f, cA2 = 0.f, cB0 = 0.f, cB1 = 0.f, cB2 = 0.f;
    if (r0 < NROW) { cA0 = __ldg(rct + r0 * 3 + 0);
                     cA1 = __ldg(rct + r0 * 3 + 1);
                     cA2 = __ldg(rct + r0 * 3 + 2); }
    if (r1 < NROW) { cB0 = __ldg(rct + r1 * 3 + 0);
                     cB1 = __ldg(rct + r1 * 3 + 1);
                     cB2 = __ldg(rct + r1 * 3 + 2); }
    __syncthreads();

    float d0[4] = {0.f, 0.f, 0.f, 0.f};   // nh 0-7 tile
    float d1[4] = {0.f, 0.f, 0.f, 0.f};   // nh 8-15 tile

    #pragma unroll 4
    for (int ch = 0; ch < 32; ch++) {
        const int h0 = ch * 16 + 2 * t;   // k positions: h0, h0+1, h0+8, h0+9
        float hA[4], hB[4];
        #pragma unroll
        for (int q = 0; q < 4; q++) {
            const int h = h0 + (q & 1) + (q >> 1) * 8;
            const float4 wc = sW14[h];
            hA[q] = fmaxf(fmaf(cA2, wc.z, fmaf(cA1, wc.y, fmaf(cA0, wc.x, wc.w))), 0.f);
            hB[q] = fmaxf(fmaf(cB2, wc.z, fmaf(cB1, wc.y, fmaf(cB0, wc.x, wc.w))), 0.f);
        }
        const unsigned a0 = bfpack(hA[0], hA[1]);
        const unsigned a1 = bfpack(hB[0], hB[1]);
        const unsigned a2 = bfpack(hA[2], hA[3]);
        const unsigned a3 = bfpack(hB[2], hB[3]);
        const unsigned bA0 = *reinterpret_cast<const unsigned*>(&sW2T[g * W2TS + h0]);
        const unsigned bA1 = *reinterpret_cast<const unsigned*>(&sW2T[g * W2TS + h0 + 8]);
        const unsigned bB0 = *reinterpret_cast<const unsigned*>(&sW2T[(g + 8) * W2TS + h0]);
        const unsigned bB1 = *reinterpret_cast<const unsigned*>(&sW2T[(g + 8) * W2TS + h0 + 8]);
        asm volatile(
            "mma.sync.aligned.m16n8k16.row.col.f32.bf16.bf16.f32 "
            "{%0,%1,%2,%3}, {%4,%5,%6,%7}, {%8,%9}, {%0,%1,%2,%3};"
            : "+f"(d0[0]), "+f"(d0[1]), "+f"(d0[2]), "+f"(d0[3])
            : "r"(a0), "r"(a1), "r"(a2), "r"(a3), "r"(bA0), "r"(bA1));
        asm volatile(
            "mma.sync.aligned.m16n8k16.row.col.f32.bf16.bf16.f32 "
            "{%0,%1,%2,%3}, {%4,%5,%6,%7}, {%8,%9}, {%0,%1,%2,%3};"
            : "+f"(d1[0]), "+f"(d1[1]), "+f"(d1[2]), "+f"(d1[3])
            : "r"(a0), "r"(a1), "r"(a2), "r"(a3), "r"(bB0), "r"(bB1));
    }

    #pragma unroll
    for (int j = 0; j < 4; j++) {
        d0[j] = 16.f / (1.f + __expf(-d0[j]));
        d1[j] = 16.f / (1.f + __expf(-d1[j]));
    }
    const int nh0 = 2 * t;
    g_rpt[(nh0    ) * NROWP + r0] = d0[0];
    g_rpt[(nh0 + 1) * NROWP + r0] = d0[1];
    g_rpt[(nh0    ) * NROWP + r1] = d0[2];
    g_rpt[(nh0 + 1) * NROWP + r1] = d0[3];
    g_rpt[(nh0 + 8) * NROWP + r0] = d1[0];
    g_rpt[(nh0 + 9) * NROWP + r0] = d1[1];
    g_rpt[(nh0 + 8) * NROWP + r1] = d1[2];
    g_rpt[(nh0 + 9) * NROWP + r1] = d1[3];
}

// ---------------------------------------------------------------------------
// Kernel 2: gather (R8/R10 winner, __stcs). MLP-independent prologue first,
// then cudaGridDependencySynchronize() (waits for MLP completion+visibility),
// then the table reads and the streaming store loop.
//   idx = (t_f + t_p)*225 + (hf-hp+7)*15 + (wf-wp+7)
// ---------------------------------------------------------------------------
__global__ void __launch_bounds__(256) gather_kernel(
    const int* __restrict__ ptc,     // [B, 8] (non-positive; time = -ptc)
    const int* __restrict__ ftc,     // [B, 8]
    float4* __restrict__ out)        // [B, 16, 512, 512] / 4
{
    __shared__ float4 vtab[240];     // [wf][dh+7][par] : wf*30 + dh7*2 + par
    const int tid = threadIdx.x;
    const int blk = blockIdx.x;
    const int tp = blk & 7;
    const int tf = (blk >> 3) & 7;
    const int nh = (blk >> 6) & 15;
    const int b  = blk >> 10;

    // --- MLP-independent prologue (overlaps with MLP under PDL) ---
    const int t_f =  __ldg(ftc + b * 8 + tf);
    const int t_p = -__ldg(ptc + b * 8 + tp);

    const int c4    = tid & 15;
    const int fhw0  = tid >> 4;            // 0..15
    const int wf    = fhw0 & 7;
    const int b0    = fhw0 >> 3;           // 0 or 1
    const int hp    = c4 >> 1;
    const int par   = c4 & 1;
    const int base0 = wf * 30 + (b0 - hp + 7) * 2 + par;   // k=0 index

    float4* __restrict__ p =
        out + ((((b * NHEAD + nh) * 512 + tf * 64) * 512 + tp * 64) >> 2)
            + fhw0 * 128 + c4;

    int vwf = 0, vsi = 0;
    if (tid < 240) {
        vwf = tid / 30;
        const int rem = tid - vwf * 30;
        const int dh7 = rem >> 1;
        const int vpar = rem & 1;                      // wp0 = vpar*4
        vsi = dh7 * 15 + vwf - vpar * 4 + 7;           // in [3, 224]
    }

#if __CUDA_ARCH__ >= 900
    cudaGridDependencySynchronize();   // wait for MLP grid completion
#endif

    const float* __restrict__ src = g_rpt + nh * NROWP + (t_f + t_p) * 225;
    if (tid < 240) {
        vtab[tid] = make_float4(__ldg(src + vsi),     __ldg(src + vsi - 1),
                                __ldg(src + vsi - 2), __ldg(src + vsi - 3));
    }
    __syncthreads();

    #pragma unroll
    for (int k = 0; k < 4; k++) {
        __stcs(p, vtab[base0 + 4 * k]);    // hf = b0 + 2k, always <= 7
        p += 2048;                          // fhw += 16
    }
}

// ---------------------------------------------------------------------------
// Launch. Input order: ptc, ftc, W1, b1, W2, rct, rpi_table (unused).
// MLP launched normally; gather launched with the PDL attribute so its grid
// is scheduled while the MLP runs (falls back to plain serialization if
// unsupported).
// ---------------------------------------------------------------------------
extern "C" void kernel_launch(void* const* d_in, const int* in_sizes, int n_in,
                              void* d_out, int out_size)
{
    const int*   ptc = (const int*)  d_in[0];
    const int*   ftc = (const int*)  d_in[1];
    const float* W1  = (const float*)d_in[2];
    const float* b1  = (const float*)d_in[3];
    const float* W2  = (const float*)d_in[4];
    const float* rct = (const float*)d_in[5];

    // 350 blocks x 64 rows = 22400 (NROWP); rows >= NROW are never read.
    mlp_kernel<<<NROWP / 64, 128>>>(rct, W1, b1, W2);

    // Gather with programmatic dependent launch.
    cudaLaunchConfig_t cfg = {};
    cfg.gridDim  = dim3(8 * NHEAD * 8 * 8);
    cfg.blockDim = dim3(256);
    cfg.dynamicSmemBytes = 0;
    cfg.stream = 0;
    cudaLaunchAttribute attr[1];
    attr[0].id = cudaLaunchAttributeProgrammaticStreamSerialization;
    attr[0].val.programmaticStreamSerializationAllowed = 1;
    cfg.attrs = attr;
    cfg.numAttrs = 1;
    cudaLaunchKernelEx(&cfg, gather_kernel, ptc, ftc, (float4*)d_out);
}